// round 4
// baseline (speedup 1.0000x reference)
#include <cuda_runtime.h>
#include <cuda_fp16.h>
#include <cstdint>

// ---------------------------------------------------------------------------
// MultiShapeNet: h = sin(x@Wpre + bpre); 8 blocks of
//   h = gamma*h + beta;  r = sin(h@W0+b0); r = sin(r@W1+b1); h = 0.5*(h+r)
// N=262144, HIDDEN=128, fp32 in/out, rel_err < 1e-3.
//
// Strategy: fused persistent-tile kernel, 128 rows/CTA, activations live in
// mma.sync accumulator fragments. GEMMs via fp16 3-term split (hi*hi + lo*hi
// + hi*lo, fp32 accumulate) -> ~fp32 accuracy at 3x bf16 FLOPs.
// Weights pre-split to fp16 hi/lo by a prep kernel, double-buffered in smem
// via cp.async with one-layer-ahead prefetch.
// ---------------------------------------------------------------------------

#define NPTS      262144
#define HID       128
#define NLAYERS16 16            // 8 blocks * 2 layers
#define WPAD      136           // halves per padded weight row
#define W_PITCH_B (WPAD*2)      // 272 bytes
#define WBUF_B    (128*W_PITCH_B)   // 34816 bytes per (hi or lo) matrix
#define WLAYER_B  (2*WBUF_B)        // 69632 bytes per buffered layer (hi+lo)

// smem layout (bytes)
#define SM_WBUF   0                         // 2 layers * (hi+lo) = 139264
#define SM_WPRE   (2*WLAYER_B)              // 139264 : 4*128 fp32 = 2048
#define SM_BPRE   (SM_WPRE + 2048)          // 141312 : 128 fp32 = 512
#define SM_HFILM  (SM_BPRE + 512)           // 141824 : 128 rows * 132 fp32
#define HF_PITCH  132
#define SMEM_TOTAL (SM_HFILM + 128*HF_PITCH*4)  // 209408 bytes

// fp16 hi/lo split of all 16 layer weight matrices, padded rows
__device__ __half g_Whi[NLAYERS16*128*WPAD];
__device__ __half g_Wlo[NLAYERS16*128*WPAD];

// ---------------------------------------------------------------------------
// prep: split W_blocks [8,2,128,128] fp32 -> hi/lo fp16, padded to 136 cols
// ---------------------------------------------------------------------------
__global__ void msnet_prep_kernel(const float* __restrict__ Wb) {
    int t = blockIdx.x * blockDim.x + threadIdx.x;
    if (t < NLAYERS16*128*128) {
        int L = t >> 14;            // layer 0..15
        int rem = t & 16383;
        int k = rem >> 7;
        int n = rem & 127;
        float w = Wb[t];            // [L][k][n] flat == t
        __half hi = __float2half_rn(w);
        float hif = __half2float(hi);
        __half lo = __float2half_rn(w - hif);
        int di = (L*128 + k)*WPAD + n;
        g_Whi[di] = hi;
        g_Wlo[di] = lo;
    }
    // zero the pad columns (cols 128..135): 16*128*8 = 16384 entries
    if (t < NLAYERS16*128*8) {
        int L = t >> 10;
        int k = (t >> 3) & 127;
        int n = 128 + (t & 7);
        int di = (L*128 + k)*WPAD + n;
        g_Whi[di] = __float2half_rn(0.f);
        g_Wlo[di] = __float2half_rn(0.f);
    }
}

// ---------------------------------------------------------------------------
// device helpers
// ---------------------------------------------------------------------------
#define LDSM_T4(r0,r1,r2,r3,addr) \
    asm volatile("ldmatrix.sync.aligned.m8n8.x4.trans.shared.b16 {%0,%1,%2,%3},[%4];\n" \
                 : "=r"(r0), "=r"(r1), "=r"(r2), "=r"(r3) : "r"(addr))

#define MMA16816(d0,d1,d2,d3,a0,a1,a2,a3,b0,b1) \
    asm volatile("mma.sync.aligned.m16n8k16.row.col.f32.f16.f16.f32 " \
                 "{%0,%1,%2,%3},{%4,%5,%6,%7},{%8,%9},{%0,%1,%2,%3};\n" \
                 : "+f"(d0), "+f"(d1), "+f"(d2), "+f"(d3) \
                 : "r"(a0), "r"(a1), "r"(a2), "r"(a3), "r"(b0), "r"(b1))

__device__ __forceinline__ void cp16(uint32_t smem_dst, const void* gsrc) {
    unsigned long long g = (unsigned long long)__cvta_generic_to_global(gsrc);
    asm volatile("cp.async.cg.shared.global [%0], [%1], 16;\n" :: "r"(smem_dst), "l"(g));
}
__device__ __forceinline__ void cp_commit() { asm volatile("cp.async.commit_group;\n"); }
__device__ __forceinline__ void cp_wait_all() { asm volatile("cp.async.wait_group 0;\n" ::: "memory"); }

// split two fp32 into packed half2 hi + half2 lo
__device__ __forceinline__ void split2(float a, float b, uint32_t& hi, uint32_t& lo) {
    __half2 h = __floats2half2_rn(a, b);        // .x = a (low half)
    float2 f = __half22float2(h);
    __half2 l = __floats2half2_rn(a - f.x, b - f.y);
    hi = *reinterpret_cast<uint32_t*>(&h);
    lo = *reinterpret_cast<uint32_t*>(&l);
}

// prefetch fp16 hi/lo weights of layer L into smem buffer (L&1)
__device__ __forceinline__ void prefetch_w(int L, uint32_t sbase, int tid) {
    const char* sh = (const char*)g_Whi + (size_t)L * WBUF_B;
    const char* sl = (const char*)g_Wlo + (size_t)L * WBUF_B;
    uint32_t dh = sbase + SM_WBUF + (uint32_t)(L & 1) * WLAYER_B;
    uint32_t dl = dh + WBUF_B;
    #pragma unroll 1
    for (int i = tid; i < WBUF_B/16; i += 256) {   // 2176 chunks of 16B
        cp16(dh + i*16, sh + i*16);
        cp16(dl + i*16, sl + i*16);
    }
    cp_commit();
}

// One 128x128x128 GEMM (3-term fp16 split) + bias + sin, per warp slab of 16
// rows. Inputs: A fragments fhi/flo [kc][4]. Output: rt[16][4] = sin(A@W + b).
__device__ __forceinline__ void gemm_sin(
    const uint32_t fhi[8][4], const uint32_t flo[8][4],
    uint32_t whi_base,          // smem addr of hi matrix + per-lane ldmatrix off
    const float* __restrict__ bias, int gc, float rt[16][4])
{
    #pragma unroll
    for (int ntp = 0; ntp < 8; ntp++) {
        float2 ba = *(const float2*)(bias + ntp*16 + gc);
        float2 bb = *(const float2*)(bias + ntp*16 + 8 + gc);
        float a0 = ba.x, a1 = ba.y, a2 = ba.x, a3 = ba.y;   // n-tile 2*ntp
        float c0 = bb.x, c1 = bb.y, c2 = bb.x, c3 = bb.y;   // n-tile 2*ntp+1
        #pragma unroll
        for (int kc = 0; kc < 8; kc++) {
            uint32_t ah = whi_base + (uint32_t)(ntp*32 + kc*16*W_PITCH_B);
            uint32_t al = ah + WBUF_B;
            uint32_t h0, h1, h2, h3, l0, l1, l2, l3;
            LDSM_T4(h0, h1, h2, h3, ah);
            LDSM_T4(l0, l1, l2, l3, al);
            // n-tile A: 3-term split
            MMA16816(a0,a1,a2,a3, fhi[kc][0],fhi[kc][1],fhi[kc][2],fhi[kc][3], h0,h1);
            MMA16816(a0,a1,a2,a3, flo[kc][0],flo[kc][1],flo[kc][2],flo[kc][3], h0,h1);
            MMA16816(a0,a1,a2,a3, fhi[kc][0],fhi[kc][1],fhi[kc][2],fhi[kc][3], l0,l1);
            // n-tile B
            MMA16816(c0,c1,c2,c3, fhi[kc][0],fhi[kc][1],fhi[kc][2],fhi[kc][3], h2,h3);
            MMA16816(c0,c1,c2,c3, flo[kc][0],flo[kc][1],flo[kc][2],flo[kc][3], h2,h3);
            MMA16816(c0,c1,c2,c3, fhi[kc][0],fhi[kc][1],fhi[kc][2],fhi[kc][3], l2,l3);
        }
        rt[2*ntp  ][0] = __sinf(a0); rt[2*ntp  ][1] = __sinf(a1);
        rt[2*ntp  ][2] = __sinf(a2); rt[2*ntp  ][3] = __sinf(a3);
        rt[2*ntp+1][0] = __sinf(c0); rt[2*ntp+1][1] = __sinf(c1);
        rt[2*ntp+1][2] = __sinf(c2); rt[2*ntp+1][3] = __sinf(c3);
    }
}

// ---------------------------------------------------------------------------
// main fused kernel: 256 threads, 128 rows per CTA
// ---------------------------------------------------------------------------
__global__ void __launch_bounds__(256, 1) msnet_kernel(
    const float* __restrict__ x,
    const float* __restrict__ gammas,
    const float* __restrict__ betas,
    const float* __restrict__ W_pre,
    const float* __restrict__ b_pre,
    const float* __restrict__ b_blocks,
    float* __restrict__ out)
{
    extern __shared__ char smem[];
    uint32_t sbase = (uint32_t)__cvta_generic_to_shared(smem);

    int tid  = threadIdx.x;
    int lane = tid & 31;
    int warp = tid >> 5;
    int gr = lane >> 2;            // group row 0..7
    int gc = (lane & 3) * 2;       // group col {0,2,4,6}

    int p0 = blockIdx.x * 128 + warp * 16 + gr;   // global point row
    int p1 = p0 + 8;
    int lr0 = warp * 16 + gr;                     // local row in CTA tile

    // per-lane ldmatrix address offset: lanes 0-15 rows, lanes 16-31 +8 cols
    uint32_t lane_off = (uint32_t)((lane & 15) * W_PITCH_B + (lane >> 4) * 16);

    // --- stage Wpre/bpre into smem, start weight prefetch for layer 0 ---
    float* sWpre = (float*)(smem + SM_WPRE);
    float* sBpre = (float*)(smem + SM_BPRE);
    for (int i = tid; i < 512; i += 256) sWpre[i] = W_pre[i];
    if (tid < 128) sBpre[tid] = b_pre[tid];
    prefetch_w(0, sbase, tid);
    __syncthreads();   // Wpre/bpre visible (BAR drains STS)

    // --- pre-layer: h = sin(x @ Wpre + bpre), K=4 via FFMA ---
    float4 xva = ((const float4*)x)[p0];
    float4 xvb = ((const float4*)x)[p1];
    float xr0[4] = {xva.x, xva.y, xva.z, xva.w};
    float xr1[4] = {xvb.x, xvb.y, xvb.z, xvb.w};

    float h[16][4];
    #pragma unroll
    for (int nt = 0; nt < 16; nt++) {
        int c = nt * 8 + gc;
        float t0 = sBpre[c], t1 = sBpre[c+1];
        float t2 = t0, t3 = t1;
        #pragma unroll
        for (int d = 0; d < 4; d++) {
            float w0 = sWpre[d*128 + c], w1 = sWpre[d*128 + c + 1];
            t0 = fmaf(xr0[d], w0, t0); t1 = fmaf(xr0[d], w1, t1);
            t2 = fmaf(xr1[d], w0, t2); t3 = fmaf(xr1[d], w1, t3);
        }
        h[nt][0] = __sinf(t0); h[nt][1] = __sinf(t1);
        h[nt][2] = __sinf(t2); h[nt][3] = __sinf(t3);
    }
    cp_wait_all();
    __syncthreads();   // layer-0 weights ready

    float* hfw = (float*)(smem + SM_HFILM);

    #pragma unroll 1
    for (int blk = 0; blk < 8; blk++) {
        uint32_t fhi[8][4], flo[8][4];

        // ---- FiLM: h_film = gamma*h + beta; stash to smem; build A frags ----
        const float* gP0 = gammas + (size_t)p0 * 1024 + blk * 128;
        const float* gP1 = gammas + (size_t)p1 * 1024 + blk * 128;
        const float* bP0 = betas  + (size_t)p0 * 1024 + blk * 128;
        const float* bP1 = betas  + (size_t)p1 * 1024 + blk * 128;
        #pragma unroll
        for (int nt = 0; nt < 16; nt++) {
            int c = nt * 8 + gc;
            float2 g0 = __ldcs((const float2*)(gP0 + c));
            float2 g1 = __ldcs((const float2*)(gP1 + c));
            float2 e0 = __ldcs((const float2*)(bP0 + c));
            float2 e1 = __ldcs((const float2*)(bP1 + c));
            float f0 = fmaf(g0.x, h[nt][0], e0.x);
            float f1 = fmaf(g0.y, h[nt][1], e0.y);
            float f2 = fmaf(g1.x, h[nt][2], e1.x);
            float f3 = fmaf(g1.y, h[nt][3], e1.y);
            *(float2*)&hfw[lr0*HF_PITCH + c]       = make_float2(f0, f1);
            *(float2*)&hfw[(lr0+8)*HF_PITCH + c]   = make_float2(f2, f3);
            int kc = nt >> 1, e = (nt & 1) * 2;
            split2(f0, f1, fhi[kc][e],   flo[kc][e]);
            split2(f2, f3, fhi[kc][e+1], flo[kc][e+1]);
        }

        // ---- layer 0 of block ----
        {
            int L = 2 * blk;
            prefetch_w(L + 1, sbase, tid);   // hide behind GEMM
            uint32_t whb = sbase + SM_WBUF + (uint32_t)(L & 1) * WLAYER_B + lane_off;
            float rt[16][4];
            gemm_sin(fhi, flo, whb, b_blocks + L * 128, gc, rt);
            #pragma unroll
            for (int nt = 0; nt < 16; nt++) {
                int kc = nt >> 1, e = (nt & 1) * 2;
                split2(rt[nt][0], rt[nt][1], fhi[kc][e],   flo[kc][e]);
                split2(rt[nt][2], rt[nt][3], fhi[kc][e+1], flo[kc][e+1]);
            }
            cp_wait_all();
            __syncthreads();
        }

        // ---- layer 1 of block + residual merge ----
        {
            int L = 2 * blk + 1;
            if (L < 15) prefetch_w(L + 1, sbase, tid);
            uint32_t whb = sbase + SM_WBUF + (uint32_t)(L & 1) * WLAYER_B + lane_off;
            float rt[16][4];
            gemm_sin(fhi, flo, whb, b_blocks + L * 128, gc, rt);
            #pragma unroll
            for (int nt = 0; nt < 16; nt++) {
                int c = nt * 8 + gc;
                float2 ha = *(float2*)&hfw[lr0*HF_PITCH + c];
                float2 hb = *(float2*)&hfw[(lr0+8)*HF_PITCH + c];
                h[nt][0] = 0.5f * (ha.x + rt[nt][0]);
                h[nt][1] = 0.5f * (ha.y + rt[nt][1]);
                h[nt][2] = 0.5f * (hb.x + rt[nt][2]);
                h[nt][3] = 0.5f * (hb.y + rt[nt][3]);
            }
            cp_wait_all();
            __syncthreads();
        }
    }

    // ---- write output [N,128] fp32 ----
    #pragma unroll
    for (int nt = 0; nt < 16; nt++) {
        int c = nt * 8 + gc;
        *(float2*)&out[(size_t)p0 * 128 + c] = make_float2(h[nt][0], h[nt][1]);
        *(float2*)&out[(size_t)p1 * 128 + c] = make_float2(h[nt][2], h[nt][3]);
    }
}

// ---------------------------------------------------------------------------
extern "C" void kernel_launch(void* const* d_in, const int* in_sizes, int n_in,
                              void* d_out, int out_size) {
    const float* x        = (const float*)d_in[0];
    const float* gammas   = (const float*)d_in[1];
    const float* betas    = (const float*)d_in[2];
    const float* W_pre    = (const float*)d_in[3];
    const float* b_pre    = (const float*)d_in[4];
    const float* W_blocks = (const float*)d_in[5];
    const float* b_blocks = (const float*)d_in[6];
    float* out = (float*)d_out;

    int N = in_sizes[0] / 4;   // 262144

    // split weights into fp16 hi/lo scratch (deterministic, every call)
    msnet_prep_kernel<<<(NLAYERS16*128*128 + 255) / 256, 256>>>(W_blocks);

    cudaFuncSetAttribute(msnet_kernel,
                         cudaFuncAttributeMaxDynamicSharedMemorySize, SMEM_TOTAL);
    msnet_kernel<<<N / 128, 256, SMEM_TOTAL>>>(
        x, gammas, betas, W_pre, b_pre, b_blocks, out);
}

// round 5
// speedup vs baseline: 1.0022x; 1.0022x over previous
#include <cuda_runtime.h>
#include <cuda_fp16.h>
#include <cstdint>

// ---------------------------------------------------------------------------
// MultiShapeNet: h = sin(x@Wpre + bpre); 8 blocks of
//   h = gamma*h + beta;  r = sin(h@W0+b0); r = sin(r@W1+b1); h = 0.5*(h+r)
// N=262144, HIDDEN=128, fp32 in/out, rel_err < 1e-3.
//
// Fused persistent-tile kernel, 128 rows/CTA, activations in mma.sync
// accumulator fragments. GEMMs via fp16 3-term split (hi*hi + lo*hi + hi*lo,
// fp32 accumulate). Weights pre-split to fp16 hi/lo, double-buffered in smem
// via cp.async with one-layer-ahead prefetch.
//
// R5 change: gemm loop nest swapped to kc-outer / n-tile-inner so all 16
// accumulator quads form independent MMA chains (was 2 chains of depth 24 ->
// latency-bound at tensor=36.7%).
// ---------------------------------------------------------------------------

#define NPTS      262144
#define HID       128
#define NLAYERS16 16            // 8 blocks * 2 layers
#define WPAD      136           // halves per padded weight row
#define W_PITCH_B (WPAD*2)      // 272 bytes
#define WBUF_B    (128*W_PITCH_B)   // 34816 bytes per (hi or lo) matrix
#define WLAYER_B  (2*WBUF_B)        // 69632 bytes per buffered layer (hi+lo)

// smem layout (bytes)
#define SM_WBUF   0                         // 2 layers * (hi+lo) = 139264
#define SM_WPRE   (2*WLAYER_B)              // 139264 : 4*128 fp32 = 2048
#define SM_BPRE   (SM_WPRE + 2048)          // 141312 : 128 fp32 = 512
#define SM_HFILM  (SM_BPRE + 512)           // 141824 : 128 rows * 132 fp32
#define HF_PITCH  132
#define SMEM_TOTAL (SM_HFILM + 128*HF_PITCH*4)  // 209408 bytes

// fp16 hi/lo split of all 16 layer weight matrices, padded rows
__device__ __half g_Whi[NLAYERS16*128*WPAD];
__device__ __half g_Wlo[NLAYERS16*128*WPAD];

// ---------------------------------------------------------------------------
// prep: split W_blocks [8,2,128,128] fp32 -> hi/lo fp16, padded to 136 cols
// ---------------------------------------------------------------------------
__global__ void msnet_prep_kernel(const float* __restrict__ Wb) {
    int t = blockIdx.x * blockDim.x + threadIdx.x;
    if (t < NLAYERS16*128*128) {
        int L = t >> 14;            // layer 0..15
        int rem = t & 16383;
        int k = rem >> 7;
        int n = rem & 127;
        float w = Wb[t];            // [L][k][n] flat == t
        __half hi = __float2half_rn(w);
        float hif = __half2float(hi);
        __half lo = __float2half_rn(w - hif);
        int di = (L*128 + k)*WPAD + n;
        g_Whi[di] = hi;
        g_Wlo[di] = lo;
    }
    // zero the pad columns (cols 128..135)
    if (t < NLAYERS16*128*8) {
        int L = t >> 10;
        int k = (t >> 3) & 127;
        int n = 128 + (t & 7);
        int di = (L*128 + k)*WPAD + n;
        g_Whi[di] = __float2half_rn(0.f);
        g_Wlo[di] = __float2half_rn(0.f);
    }
}

// ---------------------------------------------------------------------------
// device helpers
// ---------------------------------------------------------------------------
#define LDSM_T4(r0,r1,r2,r3,addr) \
    asm volatile("ldmatrix.sync.aligned.m8n8.x4.trans.shared.b16 {%0,%1,%2,%3},[%4];\n" \
                 : "=r"(r0), "=r"(r1), "=r"(r2), "=r"(r3) : "r"(addr))

#define MMA16816(d0,d1,d2,d3,a0,a1,a2,a3,b0,b1) \
    asm volatile("mma.sync.aligned.m16n8k16.row.col.f32.f16.f16.f32 " \
                 "{%0,%1,%2,%3},{%4,%5,%6,%7},{%8,%9},{%0,%1,%2,%3};\n" \
                 : "+f"(d0), "+f"(d1), "+f"(d2), "+f"(d3) \
                 : "r"(a0), "r"(a1), "r"(a2), "r"(a3), "r"(b0), "r"(b1))

__device__ __forceinline__ void cp16(uint32_t smem_dst, const void* gsrc) {
    unsigned long long g = (unsigned long long)__cvta_generic_to_global(gsrc);
    asm volatile("cp.async.cg.shared.global [%0], [%1], 16;\n" :: "r"(smem_dst), "l"(g));
}
__device__ __forceinline__ void cp_commit() { asm volatile("cp.async.commit_group;\n"); }
__device__ __forceinline__ void cp_wait_all() { asm volatile("cp.async.wait_group 0;\n" ::: "memory"); }

// split two fp32 into packed half2 hi + half2 lo
__device__ __forceinline__ void split2(float a, float b, uint32_t& hi, uint32_t& lo) {
    __half2 h = __floats2half2_rn(a, b);        // .x = a (low half)
    float2 f = __half22float2(h);
    __half2 l = __floats2half2_rn(a - f.x, b - f.y);
    hi = *reinterpret_cast<uint32_t*>(&h);
    lo = *reinterpret_cast<uint32_t*>(&l);
}

// prefetch fp16 hi/lo weights of layer L into smem buffer (L&1)
__device__ __forceinline__ void prefetch_w(int L, uint32_t sbase, int tid) {
    const char* sh = (const char*)g_Whi + (size_t)L * WBUF_B;
    const char* sl = (const char*)g_Wlo + (size_t)L * WBUF_B;
    uint32_t dh = sbase + SM_WBUF + (uint32_t)(L & 1) * WLAYER_B;
    uint32_t dl = dh + WBUF_B;
    #pragma unroll 1
    for (int i = tid; i < WBUF_B/16; i += 256) {   // 2176 chunks of 16B
        cp16(dh + i*16, sh + i*16);
        cp16(dl + i*16, sl + i*16);
    }
    cp_commit();
}

// One 128x128x128 GEMM (3-term fp16 split) + bias + sin, per warp slab of 16
// rows. kc-outer / ntp-inner: 16 independent accumulator chains for ILP.
__device__ __forceinline__ void gemm_sin(
    const uint32_t fhi[8][4], const uint32_t flo[8][4],
    uint32_t whi_base,          // smem addr of hi matrix + per-lane ldmatrix off
    const float* __restrict__ bias, int gc, float rt[16][4])
{
    float acc[16][4];
    #pragma unroll
    for (int nt = 0; nt < 16; nt++) {
        float2 b = *(const float2*)(bias + nt*8 + gc);
        acc[nt][0] = b.x; acc[nt][1] = b.y;
        acc[nt][2] = b.x; acc[nt][3] = b.y;
    }
    #pragma unroll
    for (int kc = 0; kc < 8; kc++) {
        #pragma unroll
        for (int ntp = 0; ntp < 8; ntp++) {
            uint32_t ah = whi_base + (uint32_t)(ntp*32 + kc*16*W_PITCH_B);
            uint32_t al = ah + WBUF_B;
            uint32_t h0, h1, h2, h3, l0, l1, l2, l3;
            LDSM_T4(h0, h1, h2, h3, ah);
            LDSM_T4(l0, l1, l2, l3, al);
            int na = 2*ntp, nb = 2*ntp + 1;
            MMA16816(acc[na][0],acc[na][1],acc[na][2],acc[na][3],
                     fhi[kc][0],fhi[kc][1],fhi[kc][2],fhi[kc][3], h0,h1);
            MMA16816(acc[nb][0],acc[nb][1],acc[nb][2],acc[nb][3],
                     fhi[kc][0],fhi[kc][1],fhi[kc][2],fhi[kc][3], h2,h3);
            MMA16816(acc[na][0],acc[na][1],acc[na][2],acc[na][3],
                     flo[kc][0],flo[kc][1],flo[kc][2],flo[kc][3], h0,h1);
            MMA16816(acc[nb][0],acc[nb][1],acc[nb][2],acc[nb][3],
                     flo[kc][0],flo[kc][1],flo[kc][2],flo[kc][3], h2,h3);
            MMA16816(acc[na][0],acc[na][1],acc[na][2],acc[na][3],
                     fhi[kc][0],fhi[kc][1],fhi[kc][2],fhi[kc][3], l0,l1);
            MMA16816(acc[nb][0],acc[nb][1],acc[nb][2],acc[nb][3],
                     fhi[kc][0],fhi[kc][1],fhi[kc][2],fhi[kc][3], l2,l3);
        }
    }
    #pragma unroll
    for (int nt = 0; nt < 16; nt++) {
        rt[nt][0] = __sinf(acc[nt][0]); rt[nt][1] = __sinf(acc[nt][1]);
        rt[nt][2] = __sinf(acc[nt][2]); rt[nt][3] = __sinf(acc[nt][3]);
    }
}

// ---------------------------------------------------------------------------
// main fused kernel: 256 threads, 128 rows per CTA
// ---------------------------------------------------------------------------
__global__ void __launch_bounds__(256, 1) msnet_kernel(
    const float* __restrict__ x,
    const float* __restrict__ gammas,
    const float* __restrict__ betas,
    const float* __restrict__ W_pre,
    const float* __restrict__ b_pre,
    const float* __restrict__ b_blocks,
    float* __restrict__ out)
{
    extern __shared__ char smem[];
    uint32_t sbase = (uint32_t)__cvta_generic_to_shared(smem);

    int tid  = threadIdx.x;
    int lane = tid & 31;
    int warp = tid >> 5;
    int gr = lane >> 2;            // group row 0..7
    int gc = (lane & 3) * 2;       // group col {0,2,4,6}

    int p0 = blockIdx.x * 128 + warp * 16 + gr;   // global point row
    int p1 = p0 + 8;
    int lr0 = warp * 16 + gr;                     // local row in CTA tile

    // per-lane ldmatrix address offset: lanes 0-15 rows, lanes 16-31 +8 cols
    uint32_t lane_off = (uint32_t)((lane & 15) * W_PITCH_B + (lane >> 4) * 16);

    // --- stage Wpre/bpre into smem, start weight prefetch for layer 0 ---
    float* sWpre = (float*)(smem + SM_WPRE);
    float* sBpre = (float*)(smem + SM_BPRE);
    for (int i = tid; i < 512; i += 256) sWpre[i] = W_pre[i];
    if (tid < 128) sBpre[tid] = b_pre[tid];
    prefetch_w(0, sbase, tid);
    __syncthreads();   // Wpre/bpre visible

    // --- pre-layer: h = sin(x @ Wpre + bpre), K=4 via FFMA ---
    float4 xva = ((const float4*)x)[p0];
    float4 xvb = ((const float4*)x)[p1];
    float xr0[4] = {xva.x, xva.y, xva.z, xva.w};
    float xr1[4] = {xvb.x, xvb.y, xvb.z, xvb.w};

    float h[16][4];
    #pragma unroll
    for (int nt = 0; nt < 16; nt++) {
        int c = nt * 8 + gc;
        float t0 = sBpre[c], t1 = sBpre[c+1];
        float t2 = t0, t3 = t1;
        #pragma unroll
        for (int d = 0; d < 4; d++) {
            float w0 = sWpre[d*128 + c], w1 = sWpre[d*128 + c + 1];
            t0 = fmaf(xr0[d], w0, t0); t1 = fmaf(xr0[d], w1, t1);
            t2 = fmaf(xr1[d], w0, t2); t3 = fmaf(xr1[d], w1, t3);
        }
        h[nt][0] = __sinf(t0); h[nt][1] = __sinf(t1);
        h[nt][2] = __sinf(t2); h[nt][3] = __sinf(t3);
    }
    cp_wait_all();
    __syncthreads();   // layer-0 weights ready

    float* hfw = (float*)(smem + SM_HFILM);

    #pragma unroll 1
    for (int blk = 0; blk < 8; blk++) {
        uint32_t fhi[8][4], flo[8][4];

        // ---- FiLM: h_film = gamma*h + beta; stash to smem; build A frags ----
        const float* gP0 = gammas + (size_t)p0 * 1024 + blk * 128;
        const float* gP1 = gammas + (size_t)p1 * 1024 + blk * 128;
        const float* bP0 = betas  + (size_t)p0 * 1024 + blk * 128;
        const float* bP1 = betas  + (size_t)p1 * 1024 + blk * 128;
        #pragma unroll
        for (int nt = 0; nt < 16; nt++) {
            int c = nt * 8 + gc;
            float2 g0 = __ldcs((const float2*)(gP0 + c));
            float2 g1 = __ldcs((const float2*)(gP1 + c));
            float2 e0 = __ldcs((const float2*)(bP0 + c));
            float2 e1 = __ldcs((const float2*)(bP1 + c));
            float f0 = fmaf(g0.x, h[nt][0], e0.x);
            float f1 = fmaf(g0.y, h[nt][1], e0.y);
            float f2 = fmaf(g1.x, h[nt][2], e1.x);
            float f3 = fmaf(g1.y, h[nt][3], e1.y);
            *(float2*)&hfw[lr0*HF_PITCH + c]       = make_float2(f0, f1);
            *(float2*)&hfw[(lr0+8)*HF_PITCH + c]   = make_float2(f2, f3);
            int kc = nt >> 1, e = (nt & 1) * 2;
            split2(f0, f1, fhi[kc][e],   flo[kc][e]);
            split2(f2, f3, fhi[kc][e+1], flo[kc][e+1]);
        }

        // ---- layer 0 of block ----
        {
            int L = 2 * blk;
            prefetch_w(L + 1, sbase, tid);   // hide behind GEMM
            uint32_t whb = sbase + SM_WBUF + (uint32_t)(L & 1) * WLAYER_B + lane_off;
            float rt[16][4];
            gemm_sin(fhi, flo, whb, b_blocks + L * 128, gc, rt);
            #pragma unroll
            for (int nt = 0; nt < 16; nt++) {
                int kc = nt >> 1, e = (nt & 1) * 2;
                split2(rt[nt][0], rt[nt][1], fhi[kc][e],   flo[kc][e]);
                split2(rt[nt][2], rt[nt][3], fhi[kc][e+1], flo[kc][e+1]);
            }
            cp_wait_all();
            __syncthreads();
        }

        // ---- layer 1 of block + residual merge ----
        {
            int L = 2 * blk + 1;
            if (L < 15) prefetch_w(L + 1, sbase, tid);
            uint32_t whb = sbase + SM_WBUF + (uint32_t)(L & 1) * WLAYER_B + lane_off;
            float rt[16][4];
            gemm_sin(fhi, flo, whb, b_blocks + L * 128, gc, rt);
            #pragma unroll
            for (int nt = 0; nt < 16; nt++) {
                int c = nt * 8 + gc;
                float2 ha = *(float2*)&hfw[lr0*HF_PITCH + c];
                float2 hb = *(float2*)&hfw[(lr0+8)*HF_PITCH + c];
                h[nt][0] = 0.5f * (ha.x + rt[nt][0]);
                h[nt][1] = 0.5f * (ha.y + rt[nt][1]);
                h[nt][2] = 0.5f * (hb.x + rt[nt][2]);
                h[nt][3] = 0.5f * (hb.y + rt[nt][3]);
            }
            cp_wait_all();
            __syncthreads();
        }
    }

    // ---- write output [N,128] fp32 ----
    #pragma unroll
    for (int nt = 0; nt < 16; nt++) {
        int c = nt * 8 + gc;
        *(float2*)&out[(size_t)p0 * 128 + c] = make_float2(h[nt][0], h[nt][1]);
        *(float2*)&out[(size_t)p1 * 128 + c] = make_float2(h[nt][2], h[nt][3]);
    }
}

// ---------------------------------------------------------------------------
extern "C" void kernel_launch(void* const* d_in, const int* in_sizes, int n_in,
                              void* d_out, int out_size) {
    const float* x        = (const float*)d_in[0];
    const float* gammas   = (const float*)d_in[1];
    const float* betas    = (const float*)d_in[2];
    const float* W_pre    = (const float*)d_in[3];
    const float* b_pre    = (const float*)d_in[4];
    const float* W_blocks = (const float*)d_in[5];
    const float* b_blocks = (const float*)d_in[6];
    float* out = (float*)d_out;

    int N = in_sizes[0] / 4;   // 262144

    // split weights into fp16 hi/lo scratch (deterministic, every call)
    msnet_prep_kernel<<<(NLAYERS16*128*128 + 255) / 256, 256>>>(W_blocks);

    cudaFuncSetAttribute(msnet_kernel,
                         cudaFuncAttributeMaxDynamicSharedMemorySize, SMEM_TOTAL);
    msnet_kernel<<<N / 128, 256, SMEM_TOTAL>>>(
        x, gammas, betas, W_pre, b_pre, b_blocks, out);
}

// round 7
// speedup vs baseline: 1.2338x; 1.2311x over previous
#include <cuda_runtime.h>
#include <cuda_fp16.h>
#include <cstdint>

// ---------------------------------------------------------------------------
// MultiShapeNet: h = sin(x@Wpre + bpre); 8 blocks of
//   h = gamma*h + beta;  r = sin(h@W0+b0); r = sin(r@W1+b1); h = 0.5*(h+r)
// N=262144, HIDDEN=128, fp32 in/out, rel_err < 1e-3.
//
// mma.sync fp16 3-term split (hi*hi + lo*hi + hi*lo, fp32 accumulate).
// R7: no CTA barriers in the main loop. Weights are double-buffered in smem
// via single cp.async.bulk per layer, tracked by full/empty mbarrier rings,
// so warps slip and epilogue (sin/split/FiLM LDG) overlaps sibling warps'
// tensor work. Was: global __syncthreads bubble -> tensor pipe 36.8%.
// ---------------------------------------------------------------------------

#define NLAY      16
#define WPAD      136           // halves per padded weight row
#define W_PITCH_B (WPAD*2)      // 272 bytes
#define WBUF_B    (128*W_PITCH_B)   // 34816 bytes per (hi or lo) matrix
#define WLAYER_B  (2*WBUF_B)        // 69632 bytes per layer (hi+lo)

// smem layout (bytes)
#define SM_W      0                          // 2 * 69632 = 139264
#define SM_HF     (2*WLAYER_B)               // 139264 : 128*132 fp32 = 67584
#define HF_PITCH  132
#define SM_WPRE   (SM_HF + 128*HF_PITCH*4)   // 206848 : 512 fp32
#define SM_BPRE   (SM_WPRE + 2048)           // 208896 : 128 fp32
#define SM_MBAR   (SM_BPRE + 512)            // 209408 : 4 mbarriers
#define SMEM_TOTAL (SM_MBAR + 64)            // 209472

// weights scratch: [L][hi 34816B][lo 34816B], rows padded to 136 halves
__device__ unsigned char g_W[NLAY * WLAYER_B];

// ---------------------------------------------------------------------------
// prep: W_blocks [16][128][128] fp32 -> fp16 hi/lo, padded rows, merged layout
// ---------------------------------------------------------------------------
__global__ void msnet_prep_kernel(const float* __restrict__ Wb) {
    int t = blockIdx.x * blockDim.x + threadIdx.x;
    if (t < NLAY*128*128) {
        int L = t >> 14;
        int k = (t >> 7) & 127;
        int n = t & 127;
        float w = Wb[t];
        __half hi = __float2half_rn(w);
        __half lo = __float2half_rn(w - __half2float(hi));
        __half* base = (__half*)(g_W + (size_t)L * WLAYER_B);
        base[k*WPAD + n] = hi;
        base[(WBUF_B/2) + k*WPAD + n] = lo;
    }
    if (t < NLAY*128*8) {        // zero pad columns 128..135
        int L = t >> 10;
        int k = (t >> 3) & 127;
        int n = 128 + (t & 7);
        __half* base = (__half*)(g_W + (size_t)L * WLAYER_B);
        base[k*WPAD + n] = __float2half_rn(0.f);
        base[(WBUF_B/2) + k*WPAD + n] = __float2half_rn(0.f);
    }
}

// ---------------------------------------------------------------------------
// PTX helpers
// ---------------------------------------------------------------------------
#define LDSM_T4(r0,r1,r2,r3,addr) \
    asm volatile("ldmatrix.sync.aligned.m8n8.x4.trans.shared.b16 {%0,%1,%2,%3},[%4];\n" \
                 : "=r"(r0), "=r"(r1), "=r"(r2), "=r"(r3) : "r"(addr))

#define MMA16816(d0,d1,d2,d3,a0,a1,a2,a3,b0,b1) \
    asm volatile("mma.sync.aligned.m16n8k16.row.col.f32.f16.f16.f32 " \
                 "{%0,%1,%2,%3},{%4,%5,%6,%7},{%8,%9},{%0,%1,%2,%3};\n" \
                 : "+f"(d0), "+f"(d1), "+f"(d2), "+f"(d3) \
                 : "r"(a0), "r"(a1), "r"(a2), "r"(a3), "r"(b0), "r"(b1))

#define MBAR_INIT(mb, cnt) \
    asm volatile("mbarrier.init.shared.b64 [%0], %1;" :: "r"((uint32_t)(mb)), "r"((uint32_t)(cnt)) : "memory")
#define MBAR_EXPECT_TX(mb, b) \
    asm volatile("mbarrier.arrive.expect_tx.shared.b64 _, [%0], %1;" :: "r"((uint32_t)(mb)), "r"((uint32_t)(b)) : "memory")
#define MBAR_ARRIVE(mb) \
    asm volatile("mbarrier.arrive.shared.b64 _, [%0];" :: "r"((uint32_t)(mb)) : "memory")

__device__ __forceinline__ void mbar_wait(uint32_t mb, uint32_t parity) {
    asm volatile(
        "{.reg .pred P;\n"
        "W%=:\n"
        "mbarrier.try_wait.parity.acquire.cta.shared::cta.b64 P, [%0], %1, 0x989680;\n"
        "@P bra.uni D%=;\n"
        "bra.uni W%=;\n"
        "D%=:\n}"
        :: "r"(mb), "r"(parity) : "memory");
}

__device__ __forceinline__ void bulkcp(uint32_t dst, const void* src, uint32_t bytes, uint32_t mb) {
    unsigned long long g = (unsigned long long)__cvta_generic_to_global(src);
    asm volatile("cp.async.bulk.shared::cta.global.mbarrier::complete_tx::bytes [%0], [%1], %2, [%3];"
                 :: "r"(dst), "l"(g), "r"(bytes), "r"(mb) : "memory");
}

// split two fp32 into packed half2 hi + half2 lo
__device__ __forceinline__ void split2(float a, float b, uint32_t& hi, uint32_t& lo) {
    __half2 h = __floats2half2_rn(a, b);
    float2 f = __half22float2(h);
    __half2 l = __floats2half2_rn(a - f.x, b - f.y);
    hi = *reinterpret_cast<uint32_t*>(&h);
    lo = *reinterpret_cast<uint32_t*>(&l);
}

// 128x128x128 GEMM, 3-term fp16 split, accumulate into acc (bias preloaded)
__device__ __forceinline__ void gemm_acc(
    const uint32_t fhi[8][4], const uint32_t flo[8][4],
    uint32_t whi_base, float acc[16][4])
{
    #pragma unroll
    for (int kc = 0; kc < 8; kc++) {
        #pragma unroll
        for (int ntp = 0; ntp < 8; ntp++) {
            uint32_t ah = whi_base + (uint32_t)(ntp*32 + kc*16*W_PITCH_B);
            uint32_t al = ah + WBUF_B;
            uint32_t h0, h1, h2, h3, l0, l1, l2, l3;
            LDSM_T4(h0, h1, h2, h3, ah);
            LDSM_T4(l0, l1, l2, l3, al);
            int na = 2*ntp, nb = 2*ntp + 1;
            MMA16816(acc[na][0],acc[na][1],acc[na][2],acc[na][3],
                     fhi[kc][0],fhi[kc][1],fhi[kc][2],fhi[kc][3], h0,h1);
            MMA16816(acc[nb][0],acc[nb][1],acc[nb][2],acc[nb][3],
                     fhi[kc][0],fhi[kc][1],fhi[kc][2],fhi[kc][3], h2,h3);
            MMA16816(acc[na][0],acc[na][1],acc[na][2],acc[na][3],
                     flo[kc][0],flo[kc][1],flo[kc][2],flo[kc][3], h0,h1);
            MMA16816(acc[nb][0],acc[nb][1],acc[nb][2],acc[nb][3],
                     flo[kc][0],flo[kc][1],flo[kc][2],flo[kc][3], h2,h3);
            MMA16816(acc[na][0],acc[na][1],acc[na][2],acc[na][3],
                     fhi[kc][0],fhi[kc][1],fhi[kc][2],fhi[kc][3], l0,l1);
            MMA16816(acc[nb][0],acc[nb][1],acc[nb][2],acc[nb][3],
                     fhi[kc][0],fhi[kc][1],fhi[kc][2],fhi[kc][3], l2,l3);
        }
    }
}

// ---------------------------------------------------------------------------
// main fused kernel: 256 threads, 128 rows per CTA
// ---------------------------------------------------------------------------
__global__ void __launch_bounds__(256, 1) msnet_kernel(
    const float* __restrict__ x,
    const float* __restrict__ gammas,
    const float* __restrict__ betas,
    const float* __restrict__ W_pre,
    const float* __restrict__ b_pre,
    const float* __restrict__ b_blocks,
    float* __restrict__ out)
{
    extern __shared__ char smem[];
    uint32_t sb = (uint32_t)__cvta_generic_to_shared(smem);

    int tid  = threadIdx.x;
    int lane = tid & 31;
    int warp = tid >> 5;
    int gr = lane >> 2;            // group row 0..7
    int gc = (lane & 3) * 2;       // group col {0,2,4,6}

    int p0 = blockIdx.x * 128 + warp * 16 + gr;
    int p1 = p0 + 8;
    int lr0 = warp * 16 + gr;

    uint32_t lane_off = (uint32_t)((lane & 15) * W_PITCH_B + (lane >> 4) * 16);

    uint32_t FULL0  = sb + SM_MBAR;
    uint32_t FULL1  = sb + SM_MBAR + 8;
    uint32_t EMPTY0 = sb + SM_MBAR + 16;
    uint32_t EMPTY1 = sb + SM_MBAR + 24;

    if (tid == 0) {
        MBAR_INIT(FULL0, 1);  MBAR_INIT(FULL1, 1);
        MBAR_INIT(EMPTY0, 256); MBAR_INIT(EMPTY1, 256);
    }

    float* sWpre = (float*)(smem + SM_WPRE);
    float* sBpre = (float*)(smem + SM_BPRE);
    for (int i = tid; i < 512; i += 256) sWpre[i] = W_pre[i];
    if (tid < 128) sBpre[tid] = b_pre[tid];
    __syncthreads();   // mbar init + Wpre staging visible

    // kick TMA loads for layers 0 and 1
    if (tid == 0) {
        MBAR_EXPECT_TX(FULL0, WLAYER_B);
        bulkcp(sb + SM_W, g_W, WLAYER_B, FULL0);
        MBAR_EXPECT_TX(FULL1, WLAYER_B);
        bulkcp(sb + SM_W + WLAYER_B, g_W + WLAYER_B, WLAYER_B, FULL1);
    }

    // --- pre-layer: h = sin(x @ Wpre + bpre) ---
    float4 xva = ((const float4*)x)[p0];
    float4 xvb = ((const float4*)x)[p1];
    float xr0[4] = {xva.x, xva.y, xva.z, xva.w};
    float xr1[4] = {xvb.x, xvb.y, xvb.z, xvb.w};

    float h[16][4];
    #pragma unroll
    for (int nt = 0; nt < 16; nt++) {
        int c = nt * 8 + gc;
        float t0 = sBpre[c], t1 = sBpre[c+1];
        float t2 = t0, t3 = t1;
        #pragma unroll
        for (int d = 0; d < 4; d++) {
            float w0 = sWpre[d*128 + c], w1 = sWpre[d*128 + c + 1];
            t0 = fmaf(xr0[d], w0, t0); t1 = fmaf(xr0[d], w1, t1);
            t2 = fmaf(xr1[d], w0, t2); t3 = fmaf(xr1[d], w1, t3);
        }
        h[nt][0] = __sinf(t0); h[nt][1] = __sinf(t1);
        h[nt][2] = __sinf(t2); h[nt][3] = __sinf(t3);
    }

    float* hfw = (float*)(smem + SM_HF);

    #pragma unroll 1
    for (int blk = 0; blk < 8; blk++) {
        uint32_t par = (uint32_t)(blk & 1);
        uint32_t fhi[8][4], flo[8][4];

        // ---- FiLM: f = gamma*h + beta; stash f; build A fragments ----
        const float* gP0 = gammas + (size_t)p0 * 1024 + blk * 128;
        const float* gP1 = gammas + (size_t)p1 * 1024 + blk * 128;
        const float* bP0 = betas  + (size_t)p0 * 1024 + blk * 128;
        const float* bP1 = betas  + (size_t)p1 * 1024 + blk * 128;
        #pragma unroll
        for (int nt = 0; nt < 16; nt++) {
            int c = nt * 8 + gc;
            float2 g0 = __ldcs((const float2*)(gP0 + c));
            float2 g1 = __ldcs((const float2*)(gP1 + c));
            float2 e0 = __ldcs((const float2*)(bP0 + c));
            float2 e1 = __ldcs((const float2*)(bP1 + c));
            float f0 = fmaf(g0.x, h[nt][0], e0.x);
            float f1 = fmaf(g0.y, h[nt][1], e0.y);
            float f2 = fmaf(g1.x, h[nt][2], e1.x);
            float f3 = fmaf(g1.y, h[nt][3], e1.y);
            *(float2*)&hfw[lr0*HF_PITCH + c]     = make_float2(f0, f1);
            *(float2*)&hfw[(lr0+8)*HF_PITCH + c] = make_float2(f2, f3);
            int kc = nt >> 1, e = (nt & 1) * 2;
            split2(f0, f1, fhi[kc][e],   flo[kc][e]);
            split2(f2, f3, fhi[kc][e+1], flo[kc][e+1]);
        }

        // ---- layer 0 of block (buffer 0) ----
        {
            const float* bias = b_blocks + (2*blk) * 128;
            float acc[16][4];
            #pragma unroll
            for (int nt = 0; nt < 16; nt++) {
                float2 b = *(const float2*)(bias + nt*8 + gc);
                acc[nt][0] = b.x; acc[nt][1] = b.y;
                acc[nt][2] = b.x; acc[nt][3] = b.y;
            }
            mbar_wait(FULL0, par);
            gemm_acc(fhi, flo, sb + SM_W + lane_off, acc);
            MBAR_ARRIVE(EMPTY0);
            #pragma unroll
            for (int nt = 0; nt < 16; nt++) {
                float s0 = __sinf(acc[nt][0]), s1 = __sinf(acc[nt][1]);
                float s2 = __sinf(acc[nt][2]), s3 = __sinf(acc[nt][3]);
                int kc = nt >> 1, e = (nt & 1) * 2;
                split2(s0, s1, fhi[kc][e],   flo[kc][e]);
                split2(s2, s3, fhi[kc][e+1], flo[kc][e+1]);
            }
            // refill buffer 0 with layer 2blk+2 once all warps finished reading
            if (tid == 0 && blk < 7) {
                mbar_wait(EMPTY0, par);
                MBAR_EXPECT_TX(FULL0, WLAYER_B);
                bulkcp(sb + SM_W, g_W + (size_t)(2*blk + 2) * WLAYER_B, WLAYER_B, FULL0);
            }
        }

        // ---- layer 1 of block (buffer 1) + residual merge ----
        {
            const float* bias = b_blocks + (2*blk + 1) * 128;
            float acc[16][4];
            #pragma unroll
            for (int nt = 0; nt < 16; nt++) {
                float2 b = *(const float2*)(bias + nt*8 + gc);
                acc[nt][0] = b.x; acc[nt][1] = b.y;
                acc[nt][2] = b.x; acc[nt][3] = b.y;
            }
            mbar_wait(FULL1, par);
            gemm_acc(fhi, flo, sb + SM_W + WLAYER_B + lane_off, acc);
            MBAR_ARRIVE(EMPTY1);
            #pragma unroll
            for (int nt = 0; nt < 16; nt++) {
                int c = nt * 8 + gc;
                float2 ha = *(float2*)&hfw[lr0*HF_PITCH + c];
                float2 hb = *(float2*)&hfw[(lr0+8)*HF_PITCH + c];
                h[nt][0] = 0.5f * (ha.x + __sinf(acc[nt][0]));
                h[nt][1] = 0.5f * (ha.y + __sinf(acc[nt][1]));
                h[nt][2] = 0.5f * (hb.x + __sinf(acc[nt][2]));
                h[nt][3] = 0.5f * (hb.y + __sinf(acc[nt][3]));
            }
            if (tid == 0 && blk < 7) {
                mbar_wait(EMPTY1, par);
                MBAR_EXPECT_TX(FULL1, WLAYER_B);
                bulkcp(sb + SM_W + WLAYER_B, g_W + (size_t)(2*blk + 3) * WLAYER_B, WLAYER_B, FULL1);
            }
        }
    }

    // ---- write output [N,128] fp32 ----
    #pragma unroll
    for (int nt = 0; nt < 16; nt++) {
        int c = nt * 8 + gc;
        *(float2*)&out[(size_t)p0 * 128 + c] = make_float2(h[nt][0], h[nt][1]);
        *(float2*)&out[(size_t)p1 * 128 + c] = make_float2(h[nt][2], h[nt][3]);
    }
}

// ---------------------------------------------------------------------------
extern "C" void kernel_launch(void* const* d_in, const int* in_sizes, int n_in,
                              void* d_out, int out_size) {
    const float* x        = (const float*)d_in[0];
    const float* gammas   = (const float*)d_in[1];
    const float* betas    = (const float*)d_in[2];
    const float* W_pre    = (const float*)d_in[3];
    const float* b_pre    = (const float*)d_in[4];
    const float* W_blocks = (const float*)d_in[5];
    const float* b_blocks = (const float*)d_in[6];
    float* out = (float*)d_out;

    int N = in_sizes[0] / 4;   // 262144

    msnet_prep_kernel<<<(NLAY*128*128 + 255) / 256, 256>>>(W_blocks);

    cudaFuncSetAttribute(msnet_kernel,
                         cudaFuncAttributeMaxDynamicSharedMemorySize, SMEM_TOTAL);
    msnet_kernel<<<N / 128, 256, SMEM_TOTAL>>>(
        x, gammas, betas, W_pre, b_pre, b_blocks, out);
}

// round 9
// speedup vs baseline: 1.6355x; 1.3256x over previous
#include <cuda_runtime.h>
#include <cuda_fp16.h>
#include <cstdint>

// ---------------------------------------------------------------------------
// MultiShapeNet: h = sin(x@Wpre + bpre); 8 blocks of
//   h = gamma*h + beta;  r = sin(h@W0+b0); r = sin(r@W1+b1); h = 0.5*(h+r)
// N=262144, HIDDEN=128, fp32 in/out, rel_err < 1e-3.
//
// mma.sync fp16 3-term split (hi*hi + lo*hi + hi*lo, fp32 accumulate).
// R8: (1) FiLM value f kept in h's registers (hfilm smem removed entirely),
// (2) 3-deep weight buffer ring (cp.async.bulk + mbarrier) for deeper warp
// slip, (3) GEMM split into two N-halves with half-1 sins interleaved,
// (4) biases staged in smem, (5) L2 prefetch of next block's FiLM rows.
// ---------------------------------------------------------------------------

#define NLAY      16
#define WPAD      136           // halves per padded weight row
#define W_PITCH_B (WPAD*2)      // 272 bytes
#define WBUF_B    (128*W_PITCH_B)   // 34816 bytes per (hi or lo) matrix
#define WLAYER_B  (2*WBUF_B)        // 69632 bytes per layer (hi+lo)
#define NBUF      3

// smem layout (bytes)
#define SM_W      0                          // 3 * 69632 = 208896
#define SM_BB     (NBUF*WLAYER_B)            // 208896 : 16*128 fp32 = 8192
#define SM_WPRE   (SM_BB + 8192)             // 217088 : 512 fp32
#define SM_BPRE   (SM_WPRE + 2048)           // 219136 : 128 fp32
#define SM_MBAR   (SM_BPRE + 512)            // 219648 : 6 mbarriers
#define SMEM_TOTAL (SM_MBAR + 64)            // 219712

// weights scratch: [L][hi 34816B][lo 34816B], rows padded to 136 halves
__device__ unsigned char g_W[NLAY * WLAYER_B];

// ---------------------------------------------------------------------------
// prep: W_blocks [16][128][128] fp32 -> fp16 hi/lo, padded rows
// ---------------------------------------------------------------------------
__global__ void msnet_prep_kernel(const float* __restrict__ Wb) {
    int t = blockIdx.x * blockDim.x + threadIdx.x;
    if (t < NLAY*128*128) {
        int L = t >> 14;
        int k = (t >> 7) & 127;
        int n = t & 127;
        float w = Wb[t];
        __half hi = __float2half_rn(w);
        __half lo = __float2half_rn(w - __half2float(hi));
        __half* base = (__half*)(g_W + (size_t)L * WLAYER_B);
        base[k*WPAD + n] = hi;
        base[(WBUF_B/2) + k*WPAD + n] = lo;
    }
    if (t < NLAY*128*8) {        // zero pad columns 128..135
        int L = t >> 10;
        int k = (t >> 3) & 127;
        int n = 128 + (t & 7);
        __half* base = (__half*)(g_W + (size_t)L * WLAYER_B);
        base[k*WPAD + n] = __float2half_rn(0.f);
        base[(WBUF_B/2) + k*WPAD + n] = __float2half_rn(0.f);
    }
}

// ---------------------------------------------------------------------------
// PTX helpers
// ---------------------------------------------------------------------------
#define LDSM_T4(r0,r1,r2,r3,addr) \
    asm volatile("ldmatrix.sync.aligned.m8n8.x4.trans.shared.b16 {%0,%1,%2,%3},[%4];\n" \
                 : "=r"(r0), "=r"(r1), "=r"(r2), "=r"(r3) : "r"(addr))

#define MMA16816(d0,d1,d2,d3,a0,a1,a2,a3,b0,b1) \
    asm volatile("mma.sync.aligned.m16n8k16.row.col.f32.f16.f16.f32 " \
                 "{%0,%1,%2,%3},{%4,%5,%6,%7},{%8,%9},{%0,%1,%2,%3};\n" \
                 : "+f"(d0), "+f"(d1), "+f"(d2), "+f"(d3) \
                 : "r"(a0), "r"(a1), "r"(a2), "r"(a3), "r"(b0), "r"(b1))

#define MBAR_INIT(mb, cnt) \
    asm volatile("mbarrier.init.shared.b64 [%0], %1;" :: "r"((uint32_t)(mb)), "r"((uint32_t)(cnt)) : "memory")
#define MBAR_EXPECT_TX(mb, b) \
    asm volatile("mbarrier.arrive.expect_tx.shared.b64 _, [%0], %1;" :: "r"((uint32_t)(mb)), "r"((uint32_t)(b)) : "memory")
#define MBAR_ARRIVE(mb) \
    asm volatile("mbarrier.arrive.shared.b64 _, [%0];" :: "r"((uint32_t)(mb)) : "memory")

__device__ __forceinline__ void mbar_wait(uint32_t mb, uint32_t parity) {
    asm volatile(
        "{.reg .pred P;\n"
        "W%=:\n"
        "mbarrier.try_wait.parity.acquire.cta.shared::cta.b64 P, [%0], %1, 0x989680;\n"
        "@P bra.uni D%=;\n"
        "bra.uni W%=;\n"
        "D%=:\n}"
        :: "r"(mb), "r"(parity) : "memory");
}

__device__ __forceinline__ void bulkcp(uint32_t dst, const void* src, uint32_t bytes, uint32_t mb) {
    unsigned long long g = (unsigned long long)__cvta_generic_to_global(src);
    asm volatile("cp.async.bulk.shared::cta.global.mbarrier::complete_tx::bytes [%0], [%1], %2, [%3];"
                 :: "r"(dst), "l"(g), "r"(bytes), "r"(mb) : "memory");
}

__device__ __forceinline__ void pfL2(const void* p) {
    asm volatile("prefetch.global.L2 [%0];" :: "l"(p));
}

// split two fp32 into packed half2 hi + half2 lo
__device__ __forceinline__ void split2(float a, float b, uint32_t& hi, uint32_t& lo) {
    __half2 h = __floats2half2_rn(a, b);
    float2 f = __half22float2(h);
    __half2 l = __floats2half2_rn(a - f.x, b - f.y);
    hi = *reinterpret_cast<uint32_t*>(&h);
    lo = *reinterpret_cast<uint32_t*>(&l);
}

// Half-GEMM: n-tile-pairs ntp0..ntp0+3, all 8 K-chunks, 3-term fp16 split.
// acc[8][4] covers n-tiles 2*ntp0 .. 2*ntp0+7.
__device__ __forceinline__ void gemm_half(
    const uint32_t fhi[8][4], const uint32_t flo[8][4],
    uint32_t whi_base, int ntp0, float (*acc)[4])
{
    #pragma unroll
    for (int kc = 0; kc < 8; kc++) {
        #pragma unroll
        for (int i = 0; i < 4; i++) {
            int ntp = ntp0 + i;
            uint32_t ah = whi_base + (uint32_t)(ntp*32 + kc*16*W_PITCH_B);
            uint32_t al = ah + WBUF_B;
            uint32_t h0, h1, h2, h3, l0, l1, l2, l3;
            LDSM_T4(h0, h1, h2, h3, ah);
            LDSM_T4(l0, l1, l2, l3, al);
            int na = 2*i, nb = 2*i + 1;
            MMA16816(acc[na][0],acc[na][1],acc[na][2],acc[na][3],
                     fhi[kc][0],fhi[kc][1],fhi[kc][2],fhi[kc][3], h0,h1);
            MMA16816(acc[nb][0],acc[nb][1],acc[nb][2],acc[nb][3],
                     fhi[kc][0],fhi[kc][1],fhi[kc][2],fhi[kc][3], h2,h3);
            MMA16816(acc[na][0],acc[na][1],acc[na][2],acc[na][3],
                     flo[kc][0],flo[kc][1],flo[kc][2],flo[kc][3], h0,h1);
            MMA16816(acc[nb][0],acc[nb][1],acc[nb][2],acc[nb][3],
                     flo[kc][0],flo[kc][1],flo[kc][2],flo[kc][3], h2,h3);
            MMA16816(acc[na][0],acc[na][1],acc[na][2],acc[na][3],
                     fhi[kc][0],fhi[kc][1],fhi[kc][2],fhi[kc][3], l0,l1);
            MMA16816(acc[nb][0],acc[nb][1],acc[nb][2],acc[nb][3],
                     fhi[kc][0],fhi[kc][1],fhi[kc][2],fhi[kc][3], l2,l3);
        }
    }
}

// ---------------------------------------------------------------------------
// main fused kernel: 256 threads, 128 rows per CTA
// ---------------------------------------------------------------------------
__global__ void __launch_bounds__(256, 1) msnet_kernel(
    const float* __restrict__ x,
    const float* __restrict__ gammas,
    const float* __restrict__ betas,
    const float* __restrict__ W_pre,
    const float* __restrict__ b_pre,
    const float* __restrict__ b_blocks,
    float* __restrict__ out)
{
    extern __shared__ char smem[];
    uint32_t sb = (uint32_t)__cvta_generic_to_shared(smem);

    int tid  = threadIdx.x;
    int lane = tid & 31;
    int warp = tid >> 5;
    int gr = lane >> 2;            // group row 0..7
    int gc = (lane & 3) * 2;       // group col {0,2,4,6}

    int p0 = blockIdx.x * 128 + warp * 16 + gr;
    int p1 = p0 + 8;

    uint32_t lane_off = (uint32_t)((lane & 15) * W_PITCH_B + (lane >> 4) * 16);

    if (tid == 0) {
        #pragma unroll
        for (int b = 0; b < NBUF; b++) {
            MBAR_INIT(sb + SM_MBAR + b*8, 1);        // FULL[b]
            MBAR_INIT(sb + SM_MBAR + 24 + b*8, 256); // EMPTY[b]
        }
    }

    float* sWpre = (float*)(smem + SM_WPRE);
    float* sBpre = (float*)(smem + SM_BPRE);
    float* sBB   = (float*)(smem + SM_BB);
    for (int i = tid; i < 512; i += 256) sWpre[i] = W_pre[i];
    if (tid < 128) sBpre[tid] = b_pre[tid];
    for (int i = tid; i < NLAY*128; i += 256) sBB[i] = b_blocks[i];
    __syncthreads();   // mbar init + staging visible

    // kick TMA loads for layers 0,1,2
    if (tid == 0) {
        #pragma unroll
        for (int b = 0; b < NBUF; b++) {
            MBAR_EXPECT_TX(sb + SM_MBAR + b*8, WLAYER_B);
            bulkcp(sb + SM_W + (uint32_t)b*WLAYER_B, g_W + (size_t)b*WLAYER_B,
                   WLAYER_B, sb + SM_MBAR + b*8);
        }
    }

    // --- pre-layer: h = sin(x @ Wpre + bpre) ---
    float4 xva = ((const float4*)x)[p0];
    float4 xvb = ((const float4*)x)[p1];
    float xr0[4] = {xva.x, xva.y, xva.z, xva.w};
    float xr1[4] = {xvb.x, xvb.y, xvb.z, xvb.w};

    float h[16][4];
    #pragma unroll
    for (int nt = 0; nt < 16; nt++) {
        int c = nt * 8 + gc;
        float t0 = sBpre[c], t1 = sBpre[c+1];
        float t2 = t0, t3 = t1;
        #pragma unroll
        for (int d = 0; d < 4; d++) {
            float w0 = sWpre[d*128 + c], w1 = sWpre[d*128 + c + 1];
            t0 = fmaf(xr0[d], w0, t0); t1 = fmaf(xr0[d], w1, t1);
            t2 = fmaf(xr1[d], w0, t2); t3 = fmaf(xr1[d], w1, t3);
        }
        h[nt][0] = __sinf(t0); h[nt][1] = __sinf(t1);
        h[nt][2] = __sinf(t2); h[nt][3] = __sinf(t3);
    }

    uint32_t fhi[8][4], flo[8][4];

    #pragma unroll 1
    for (int L = 0; L < NLAY; L++) {
        int b = L % 3;
        uint32_t up = (uint32_t)((L / 3) & 1);
        uint32_t FULLb  = sb + SM_MBAR + (uint32_t)b*8;
        uint32_t EMPTYb = sb + SM_MBAR + 24 + (uint32_t)b*8;

        if ((L & 1) == 0) {
            int blk = L >> 1;
            // ---- FiLM: f = gamma*h + beta; h <- f (registers); split ----
            const float* gP0 = gammas + (size_t)p0 * 1024 + blk * 128;
            const float* gP1 = gammas + (size_t)p1 * 1024 + blk * 128;
            const float* bP0 = betas  + (size_t)p0 * 1024 + blk * 128;
            const float* bP1 = betas  + (size_t)p1 * 1024 + blk * 128;
            #pragma unroll
            for (int nt = 0; nt < 16; nt++) {
                int c = nt * 8 + gc;
                float2 g0 = __ldcs((const float2*)(gP0 + c));
                float2 g1 = __ldcs((const float2*)(gP1 + c));
                float2 e0 = __ldcs((const float2*)(bP0 + c));
                float2 e1 = __ldcs((const float2*)(bP1 + c));
                h[nt][0] = fmaf(g0.x, h[nt][0], e0.x);
                h[nt][1] = fmaf(g0.y, h[nt][1], e0.y);
                h[nt][2] = fmaf(g1.x, h[nt][2], e1.x);
                h[nt][3] = fmaf(g1.y, h[nt][3], e1.y);
                int kc = nt >> 1, e = (nt & 1) * 2;
                split2(h[nt][0], h[nt][1], fhi[kc][e],   flo[kc][e]);
                split2(h[nt][2], h[nt][3], fhi[kc][e+1], flo[kc][e+1]);
            }
            // L2-prefetch next block's FiLM rows (consumed in ~2 layers)
            if (blk < 7) {
                int co = (lane & 3) * 32;
                pfL2(gammas + (size_t)p0 * 1024 + (blk+1) * 128 + co);
                pfL2(gammas + (size_t)p1 * 1024 + (blk+1) * 128 + co);
                pfL2(betas  + (size_t)p0 * 1024 + (blk+1) * 128 + co);
                pfL2(betas  + (size_t)p1 * 1024 + (blk+1) * 128 + co);
            }
        }

        // ---- bias init from smem ----
        float acc[16][4];
        const float* bias = sBB + L * 128;
        #pragma unroll
        for (int nt = 0; nt < 16; nt++) {
            float2 b2 = *(const float2*)(bias + nt*8 + gc);
            acc[nt][0] = b2.x; acc[nt][1] = b2.y;
            acc[nt][2] = b2.x; acc[nt][3] = b2.y;
        }

        mbar_wait(FULLb, up);
        uint32_t wb = sb + SM_W + (uint32_t)b * WLAYER_B + lane_off;

        gemm_half(fhi, flo, wb, 0, &acc[0]);
        // sins of half 1 — independent of half-2 MMAs, scheduler interleaves
        #pragma unroll
        for (int nt = 0; nt < 8; nt++) {
            acc[nt][0] = __sinf(acc[nt][0]); acc[nt][1] = __sinf(acc[nt][1]);
            acc[nt][2] = __sinf(acc[nt][2]); acc[nt][3] = __sinf(acc[nt][3]);
        }
        gemm_half(fhi, flo, wb, 4, &acc[8]);
        MBAR_ARRIVE(EMPTYb);
        #pragma unroll
        for (int nt = 8; nt < 16; nt++) {
            acc[nt][0] = __sinf(acc[nt][0]); acc[nt][1] = __sinf(acc[nt][1]);
            acc[nt][2] = __sinf(acc[nt][2]); acc[nt][3] = __sinf(acc[nt][3]);
        }

        if ((L & 1) == 0) {
            // r1 -> fragments for layer L+1
            #pragma unroll
            for (int nt = 0; nt < 16; nt++) {
                int kc = nt >> 1, e = (nt & 1) * 2;
                split2(acc[nt][0], acc[nt][1], fhi[kc][e],   flo[kc][e]);
                split2(acc[nt][2], acc[nt][3], fhi[kc][e+1], flo[kc][e+1]);
            }
        } else {
            // residual merge: h = 0.5*(f + r2), f is current h
            #pragma unroll
            for (int nt = 0; nt < 16; nt++) {
                h[nt][0] = 0.5f * (h[nt][0] + acc[nt][0]);
                h[nt][1] = 0.5f * (h[nt][1] + acc[nt][1]);
                h[nt][2] = 0.5f * (h[nt][2] + acc[nt][2]);
                h[nt][3] = 0.5f * (h[nt][3] + acc[nt][3]);
            }
        }

        // refill buffer b with layer L+3 once all warps done reading layer L
        if (tid == 0 && L < NLAY - 3) {
            mbar_wait(EMPTYb, up);
            MBAR_EXPECT_TX(FULLb, WLAYER_B);
            bulkcp(sb + SM_W + (uint32_t)b * WLAYER_B,
                   g_W + (size_t)(L + 3) * WLAYER_B, WLAYER_B, FULLb);
        }
    }

    // ---- write output [N,128] fp32 ----
    #pragma unroll
    for (int nt = 0; nt < 16; nt++) {
        int c = nt * 8 + gc;
        *(float2*)&out[(size_t)p0 * 128 + c] = make_float2(h[nt][0], h[nt][1]);
        *(float2*)&out[(size_t)p1 * 128 + c] = make_float2(h[nt][2], h[nt][3]);
    }
}

// ---------------------------------------------------------------------------
extern "C" void kernel_launch(void* const* d_in, const int* in_sizes, int n_in,
                              void* d_out, int out_size) {
    const float* x        = (const float*)d_in[0];
    const float* gammas   = (const float*)d_in[1];
    const float* betas    = (const float*)d_in[2];
    const float* W_pre    = (const float*)d_in[3];
    const float* b_pre    = (const float*)d_in[4];
    const float* W_blocks = (const float*)d_in[5];
    const float* b_blocks = (const float*)d_in[6];
    float* out = (float*)d_out;

    int N = in_sizes[0] / 4;   // 262144

    msnet_prep_kernel<<<(NLAY*128*128 + 255) / 256, 256>>>(W_blocks);

    cudaFuncSetAttribute(msnet_kernel,
                         cudaFuncAttributeMaxDynamicSharedMemorySize, SMEM_TOTAL);
    msnet_kernel<<<N / 128, 256, SMEM_TOTAL>>>(
        x, gammas, betas, W_pre, b_pre, b_blocks, out);
}